// round 1
// baseline (speedup 1.0000x reference)
#include <cuda_runtime.h>
#include <math.h>

#define NB 4
#define CC 256
#define HEADS 4
#define DH 64
#define LL 4096
#define GROUPS 32

// Scratch (allocation-free rule: __device__ globals)
__device__ float g_xn[NB * CC * LL];
__device__ float g_q [NB * CC * LL];
__device__ float g_k [NB * CC * LL];
__device__ float g_v [NB * CC * LL];
__device__ float g_ao[NB * CC * LL];

// ---------------------------------------------------------------------------
// GroupNorm: one block per (n, group). 8 channels x 4096 = 32768 elems/block.
// ---------------------------------------------------------------------------
__global__ void gn_kernel(const float* __restrict__ x,
                          const float* __restrict__ gamma,
                          const float* __restrict__ beta,
                          float* __restrict__ xn) {
    int n = blockIdx.x >> 5;
    int g = blockIdx.x & 31;
    const float* xp = x  + (size_t)(n * CC + g * 8) * LL;
    float*       op = xn + (size_t)(n * CC + g * 8) * LL;

    float s = 0.f, ss = 0.f;
    for (int i = threadIdx.x; i < 8 * LL; i += 256) {
        float v = xp[i];
        s += v; ss += v * v;
    }
    __shared__ float rs[256], rss[256];
    rs[threadIdx.x] = s; rss[threadIdx.x] = ss;
    __syncthreads();
    for (int o = 128; o > 0; o >>= 1) {
        if (threadIdx.x < o) {
            rs[threadIdx.x]  += rs[threadIdx.x + o];
            rss[threadIdx.x] += rss[threadIdx.x + o];
        }
        __syncthreads();
    }
    const float invN = 1.f / (8.f * LL);
    float mean = rs[0] * invN;
    float var  = rss[0] * invN - mean * mean;
    float inv  = rsqrtf(var + 1e-5f);
    for (int i = threadIdx.x; i < 8 * LL; i += 256) {
        int c = g * 8 + (i >> 12);
        op[i] = (xp[i] - mean) * inv * gamma[c] + beta[c];
    }
}

// ---------------------------------------------------------------------------
// Channel GEMM (1x1 conv): out[n][o][l] = sum_c W[o][c] * X[n][c][l] (+ bias)
// 64x64 tile, 16x16 threads, 4x4 per thread.
// ---------------------------------------------------------------------------
__global__ void proj_kernel(const float* __restrict__ W,
                            const float* __restrict__ X,
                            const float* __restrict__ bias,
                            float* __restrict__ out) {
    int n  = blockIdx.z;
    int o0 = blockIdx.y << 6;
    int l0 = blockIdx.x << 6;
    const float* Xn = X   + (size_t)n * CC * LL;
    float*       On = out + (size_t)n * CC * LL;

    __shared__ float Ws[16][65];   // Ws[kk][i] = W[o0+i][k0+kk]
    __shared__ float Xs[16][68];   // Xs[kk][j] = X[k0+kk][l0+j]  (pad 68 -> 16B aligned float4)

    int tx = threadIdx.x, ty = threadIdx.y;
    int tid = ty * 16 + tx;
    float acc[4][4] = {};

    for (int k0 = 0; k0 < CC; k0 += 16) {
        {
            int kk = tid & 15, ib = tid >> 4;
            #pragma unroll
            for (int p = 0; p < 4; p++) {
                int i = ib + p * 16;
                Ws[kk][i] = W[(o0 + i) * CC + k0 + kk];
            }
        }
        {
            int j = tid & 63, kb = tid >> 6;
            #pragma unroll
            for (int p = 0; p < 4; p++) {
                int kk = kb + p * 4;
                Xs[kk][j] = Xn[(size_t)(k0 + kk) * LL + l0 + j];
            }
        }
        __syncthreads();
        #pragma unroll
        for (int kk = 0; kk < 16; kk++) {
            float a[4];
            #pragma unroll
            for (int ii = 0; ii < 4; ii++) a[ii] = Ws[kk][ty * 4 + ii];
            float4 b4 = *reinterpret_cast<const float4*>(&Xs[kk][tx * 4]);
            float b[4] = {b4.x, b4.y, b4.z, b4.w};
            #pragma unroll
            for (int ii = 0; ii < 4; ii++)
                #pragma unroll
                for (int jj = 0; jj < 4; jj++)
                    acc[ii][jj] += a[ii] * b[jj];
        }
        __syncthreads();
    }
    #pragma unroll
    for (int ii = 0; ii < 4; ii++) {
        int o = o0 + ty * 4 + ii;
        float bb = bias ? bias[o] : 0.f;
        #pragma unroll
        for (int jj = 0; jj < 4; jj++)
            On[(size_t)o * LL + l0 + tx * 4 + jj] = acc[ii][jj] + bb;
    }
}

// ---------------------------------------------------------------------------
// Flash attention: per (n,h), 64-row tile per block, sweep 64 col-tiles.
// q/k/v stored [N][C][L] => per head a [dh][L] matrix (d-major).
// Softmax in base-2 (log2e folded into Q scale).
// ---------------------------------------------------------------------------
#define SP 68   // smem row pad (floats) -> 16B-aligned float4 rows

__global__ void attn_kernel(const float* __restrict__ q,
                            const float* __restrict__ k,
                            const float* __restrict__ v,
                            float* __restrict__ ao) {
    extern __shared__ float sm[];
    float* Qs  = sm;               // [l][d]  (64 x SP)
    float* KVs = sm + 64 * SP;     // K phase: [d][j]; V phase: [j][d]
    float* Ps  = sm + 2 * 64 * SP; // [i][j]

    int nh = blockIdx.y;
    int n = nh >> 2, h = nh & 3;
    int l0 = blockIdx.x << 6;
    const float* qb = q + ((size_t)n * CC + h * DH) * LL;
    const float* kb = k + ((size_t)n * CC + h * DH) * LL;
    const float* vb = v + ((size_t)n * CC + h * DH) * LL;

    int tx = threadIdx.x, ty = threadIdx.y;
    int tid = ty * 16 + tx;

    // Load Q tile, pre-scaled by 1/sqrt(dh) * log2(e)
    const float qscale = 0.125f * 1.44269504088896340736f;
    {
        int l = tid & 63, db = tid >> 6;
        #pragma unroll
        for (int p = 0; p < 16; p++) {
            int d = db * 16 + p;
            Qs[l * SP + d] = qb[(size_t)d * LL + l0 + l] * qscale;
        }
    }

    float m[4], lsum[4], O[4][4];
    #pragma unroll
    for (int ii = 0; ii < 4; ii++) {
        m[ii] = -INFINITY; lsum[ii] = 0.f;
        #pragma unroll
        for (int dd = 0; dd < 4; dd++) O[ii][dd] = 0.f;
    }

    for (int jt = 0; jt < LL / 64; jt++) {
        int lk = jt << 6;
        __syncthreads();  // prior V use of KVs done
        // Load K tile as [d][j]
        {
            int l = tid & 63, db = tid >> 6;
            #pragma unroll
            for (int p = 0; p < 16; p++) {
                int d = db * 16 + p;
                KVs[d * SP + l] = kb[(size_t)d * LL + lk + l];
            }
        }
        __syncthreads();

        // S = Q K^T (already includes scale*log2e)
        float s[4][4] = {};
        #pragma unroll
        for (int d = 0; d < DH; d++) {
            float a[4];
            #pragma unroll
            for (int ii = 0; ii < 4; ii++) a[ii] = Qs[(ty * 4 + ii) * SP + d];
            float4 b4 = *reinterpret_cast<const float4*>(&KVs[d * SP + tx * 4]);
            float b[4] = {b4.x, b4.y, b4.z, b4.w};
            #pragma unroll
            for (int ii = 0; ii < 4; ii++)
                #pragma unroll
                for (int jj = 0; jj < 4; jj++)
                    s[ii][jj] += a[ii] * b[jj];
        }

        // Online softmax per row (rows owned by a half-warp: same ty)
        #pragma unroll
        for (int ii = 0; ii < 4; ii++) {
            float rmax = s[ii][0];
            #pragma unroll
            for (int jj = 1; jj < 4; jj++) rmax = fmaxf(rmax, s[ii][jj]);
            #pragma unroll
            for (int o = 8; o > 0; o >>= 1)
                rmax = fmaxf(rmax, __shfl_xor_sync(0xffffffffu, rmax, o));
            float mnew = fmaxf(m[ii], rmax);
            float corr = exp2f(m[ii] - mnew);   // -inf on first tile -> 0
            lsum[ii] *= corr;
            float rs_ = 0.f;
            #pragma unroll
            for (int jj = 0; jj < 4; jj++) {
                float p = exp2f(s[ii][jj] - mnew);
                s[ii][jj] = p; rs_ += p;
            }
            #pragma unroll
            for (int o = 8; o > 0; o >>= 1)
                rs_ += __shfl_xor_sync(0xffffffffu, rs_, o);
            lsum[ii] += rs_;
            #pragma unroll
            for (int dd = 0; dd < 4; dd++) O[ii][dd] *= corr;
            m[ii] = mnew;
        }
        // Store P tile
        #pragma unroll
        for (int ii = 0; ii < 4; ii++)
            *reinterpret_cast<float4*>(&Ps[(ty * 4 + ii) * SP + tx * 4]) =
                make_float4(s[ii][0], s[ii][1], s[ii][2], s[ii][3]);
        __syncthreads();  // Ps visible; K use of KVs done

        // Load V tile as [j][d]
        {
            int l = tid & 63, db = tid >> 6;
            #pragma unroll
            for (int p = 0; p < 16; p++) {
                int d = db * 16 + p;
                KVs[l * SP + d] = vb[(size_t)d * LL + lk + l];
            }
        }
        __syncthreads();

        // O += P V
        #pragma unroll
        for (int j = 0; j < 64; j++) {
            float a[4];
            #pragma unroll
            for (int ii = 0; ii < 4; ii++) a[ii] = Ps[(ty * 4 + ii) * SP + j];
            float4 b4 = *reinterpret_cast<const float4*>(&KVs[j * SP + tx * 4]);
            float b[4] = {b4.x, b4.y, b4.z, b4.w};
            #pragma unroll
            for (int ii = 0; ii < 4; ii++)
                #pragma unroll
                for (int dd = 0; dd < 4; dd++)
                    O[ii][dd] += a[ii] * b[dd];
        }
    }

    // Normalize and write to [N][C][L] layout (c = h*DH + d)
    #pragma unroll
    for (int ii = 0; ii < 4; ii++) {
        float invl = 1.f / lsum[ii];
        int li = l0 + ty * 4 + ii;
        #pragma unroll
        for (int dd = 0; dd < 4; dd++) {
            int d = tx * 4 + dd;
            ao[((size_t)n * CC + h * DH + d) * LL + li] = O[ii][dd] * invl;
        }
    }
}

// ---------------------------------------------------------------------------
extern "C" void kernel_launch(void* const* d_in, const int* in_sizes, int n_in,
                              void* d_out, int out_size) {
    const float* x     = (const float*)d_in[0];
    const float* gamma = (const float*)d_in[1];
    const float* beta  = (const float*)d_in[2];
    const float* Wq    = (const float*)d_in[3];
    const float* Wk    = (const float*)d_in[4];
    const float* Wv    = (const float*)d_in[5];
    const float* Wp    = (const float*)d_in[6];
    const float* bp    = (const float*)d_in[7];
    float* out = (float*)d_out;

    float *xn, *q, *k, *v, *ao;
    cudaGetSymbolAddress((void**)&xn, g_xn);
    cudaGetSymbolAddress((void**)&q,  g_q);
    cudaGetSymbolAddress((void**)&k,  g_k);
    cudaGetSymbolAddress((void**)&v,  g_v);
    cudaGetSymbolAddress((void**)&ao, g_ao);

    // GroupNorm
    gn_kernel<<<NB * GROUPS, 256>>>(x, gamma, beta, xn);

    // Q/K/V projections
    dim3 pgrid(LL / 64, CC / 64, NB), pblk(16, 16);
    proj_kernel<<<pgrid, pblk>>>(Wq, xn, nullptr, q);
    proj_kernel<<<pgrid, pblk>>>(Wk, xn, nullptr, k);
    proj_kernel<<<pgrid, pblk>>>(Wv, xn, nullptr, v);

    // Flash attention
    size_t smem = 3 * 64 * SP * sizeof(float);  // 52224 B
    static bool attr_set = false;
    cudaFuncSetAttribute(attn_kernel, cudaFuncAttributeMaxDynamicSharedMemorySize, (int)smem);
    (void)attr_set;
    attn_kernel<<<dim3(LL / 64, NB * HEADS), dim3(16, 16), smem>>>(q, k, v, ao);

    // Output projection (+bias) straight into d_out
    proj_kernel<<<pgrid, pblk>>>(Wp, ao, bp, out);
}

// round 2
// speedup vs baseline: 2.4154x; 2.4154x over previous
#include <cuda_runtime.h>
#include <math.h>

#define NB 4
#define CC 256
#define HEADS 4
#define DH 64
#define LL 4096
#define GROUPS 32

// Scratch (allocation-free rule: __device__ globals)
__device__ float g_xn[NB * CC * LL];
__device__ float g_q [NB * CC * LL];
__device__ float g_k [NB * CC * LL];
__device__ float g_v [NB * CC * LL];
__device__ float g_ao[NB * CC * LL];

// ---------------------------------------------------------------------------
// helpers
// ---------------------------------------------------------------------------
__device__ __forceinline__ unsigned f2tf(float x) {
    unsigned u;
    asm("cvt.rna.tf32.f32 %0, %1;" : "=r"(u) : "f"(x));
    return u;
}
__device__ __forceinline__ float ex2f(float x) {
    float r;
    asm("ex2.approx.ftz.f32 %0, %1;" : "=f"(r) : "f"(x));
    return r;
}
__device__ __forceinline__ void mma_tf32(float* c, const unsigned* a,
                                         unsigned b0, unsigned b1) {
    asm volatile(
        "mma.sync.aligned.m16n8k8.row.col.f32.tf32.tf32.f32 "
        "{%0,%1,%2,%3}, {%4,%5,%6,%7}, {%8,%9}, {%0,%1,%2,%3};"
        : "+f"(c[0]), "+f"(c[1]), "+f"(c[2]), "+f"(c[3])
        : "r"(a[0]), "r"(a[1]), "r"(a[2]), "r"(a[3]), "r"(b0), "r"(b1));
}

// ---------------------------------------------------------------------------
// GroupNorm: one block per (n, group). 8 channels x 4096 = 32768 elems/block.
// ---------------------------------------------------------------------------
__global__ void gn_kernel(const float* __restrict__ x,
                          const float* __restrict__ gamma,
                          const float* __restrict__ beta,
                          float* __restrict__ xn) {
    int n = blockIdx.x >> 5;
    int g = blockIdx.x & 31;
    const float* xp = x  + (size_t)(n * CC + g * 8) * LL;
    float*       op = xn + (size_t)(n * CC + g * 8) * LL;

    float s = 0.f, ss = 0.f;
    for (int i = threadIdx.x; i < 8 * LL; i += 256) {
        float v = xp[i];
        s += v; ss += v * v;
    }
    __shared__ float rs[256], rss[256];
    rs[threadIdx.x] = s; rss[threadIdx.x] = ss;
    __syncthreads();
    for (int o = 128; o > 0; o >>= 1) {
        if (threadIdx.x < o) {
            rs[threadIdx.x]  += rs[threadIdx.x + o];
            rss[threadIdx.x] += rss[threadIdx.x + o];
        }
        __syncthreads();
    }
    const float invN = 1.f / (8.f * LL);
    float mean = rs[0] * invN;
    float var  = rss[0] * invN - mean * mean;
    float inv  = rsqrtf(var + 1e-5f);
    for (int i = threadIdx.x; i < 8 * LL; i += 256) {
        int c = g * 8 + (i >> 12);
        op[i] = (xp[i] - mean) * inv * gamma[c] + beta[c];
    }
}

// ---------------------------------------------------------------------------
// Channel GEMM (1x1 conv): out[n][o][l] = sum_c W[o][c] * X[n][c][l] (+ bias)
// 64x64 tile, 16x16 threads, 4x4 per thread. (unchanged this round)
// ---------------------------------------------------------------------------
__global__ void proj_kernel(const float* __restrict__ W,
                            const float* __restrict__ X,
                            const float* __restrict__ bias,
                            float* __restrict__ out) {
    int n  = blockIdx.z;
    int o0 = blockIdx.y << 6;
    int l0 = blockIdx.x << 6;
    const float* Xn = X   + (size_t)n * CC * LL;
    float*       On = out + (size_t)n * CC * LL;

    __shared__ float Ws[16][65];
    __shared__ float Xs[16][68];

    int tx = threadIdx.x, ty = threadIdx.y;
    int tid = ty * 16 + tx;
    float acc[4][4] = {};

    for (int k0 = 0; k0 < CC; k0 += 16) {
        {
            int kk = tid & 15, ib = tid >> 4;
            #pragma unroll
            for (int p = 0; p < 4; p++) {
                int i = ib + p * 16;
                Ws[kk][i] = W[(o0 + i) * CC + k0 + kk];
            }
        }
        {
            int j = tid & 63, kb = tid >> 6;
            #pragma unroll
            for (int p = 0; p < 4; p++) {
                int kk = kb + p * 4;
                Xs[kk][j] = Xn[(size_t)(k0 + kk) * LL + l0 + j];
            }
        }
        __syncthreads();
        #pragma unroll
        for (int kk = 0; kk < 16; kk++) {
            float a[4];
            #pragma unroll
            for (int ii = 0; ii < 4; ii++) a[ii] = Ws[kk][ty * 4 + ii];
            float4 b4 = *reinterpret_cast<const float4*>(&Xs[kk][tx * 4]);
            float b[4] = {b4.x, b4.y, b4.z, b4.w};
            #pragma unroll
            for (int ii = 0; ii < 4; ii++)
                #pragma unroll
                for (int jj = 0; jj < 4; jj++)
                    acc[ii][jj] += a[ii] * b[jj];
        }
        __syncthreads();
    }
    #pragma unroll
    for (int ii = 0; ii < 4; ii++) {
        int o = o0 + ty * 4 + ii;
        float bb = bias ? bias[o] : 0.f;
        #pragma unroll
        for (int jj = 0; jj < 4; jj++)
            On[(size_t)o * LL + l0 + tx * 4 + jj] = acc[ii][jj] + bb;
    }
}

// ---------------------------------------------------------------------------
// Flash attention on tensor cores (tf32 mma.sync m16n8k8).
// Per (n,h): 64-row Q tile per 128-thread block (4 warps x 16 rows),
// sweep 64 K/V column tiles of 64. All operands pre-converted to tf32 in smem.
// Pads: Ks 72 (bank = 8*t4+g, conflict-free), Vs/Ps 68 (bank = 4*g+t4).
// ---------------------------------------------------------------------------
#define PK 72
#define PV 68
#define PP 68

__global__ void attn_tc_kernel(const float* __restrict__ q,
                               const float* __restrict__ k,
                               const float* __restrict__ v,
                               float* __restrict__ ao) {
    extern __shared__ float sm[];
    float* Ks  = sm;                     // [d][j], pad PK, tf32 bits
    float* Vs  = sm + 64 * PK;           // [d][j], pad PV, tf32 bits
    float* QPs = Vs + 64 * PV;           // phase1: Q [d][i] pad PK; phase2: P [i][j] pad PP
                                         // end:   O [d][i] pad PV (staging, aliases Ks)

    int nh = blockIdx.y;
    int n = nh >> 2, h = nh & 3;
    int l0 = blockIdx.x << 6;
    const float* qb = q + ((size_t)n * CC + h * DH) * LL;
    const float* kb = k + ((size_t)n * CC + h * DH) * LL;
    const float* vb = v + ((size_t)n * CC + h * DH) * LL;

    int tid  = threadIdx.x;
    int lane = tid & 31, w = tid >> 5;
    int g = lane >> 2, t4 = lane & 3;
    int row0 = w * 16 + g;               // rows row0 and row0+8 owned by this thread

    const float qscale = 0.125f * 1.44269504088896340736f;  // dh^-0.5 * log2(e)

    // ---- load Q tile -> QPs[d][i] (pad PK), scaled + tf32-converted ----
    #pragma unroll
    for (int r = 0; r < 8; r++) {
        int idx = r * 512 + tid * 4;
        int d = idx >> 6, j = idx & 63;
        float4 xq = *reinterpret_cast<const float4*>(&qb[(size_t)d * LL + l0 + j]);
        QPs[d * PK + j + 0] = __uint_as_float(f2tf(xq.x * qscale));
        QPs[d * PK + j + 1] = __uint_as_float(f2tf(xq.y * qscale));
        QPs[d * PK + j + 2] = __uint_as_float(f2tf(xq.z * qscale));
        QPs[d * PK + j + 3] = __uint_as_float(f2tf(xq.w * qscale));
    }
    __syncthreads();

    // ---- Q fragments (A, m16k8) into registers: qa[kt][0..3] ----
    unsigned qa[8][4];
    #pragma unroll
    for (int kt = 0; kt < 8; kt++) {
        int kk = kt * 8 + t4;
        qa[kt][0] = __float_as_uint(QPs[kk * PK + row0]);
        qa[kt][1] = __float_as_uint(QPs[kk * PK + row0 + 8]);
        qa[kt][2] = __float_as_uint(QPs[(kk + 4) * PK + row0]);
        qa[kt][3] = __float_as_uint(QPs[(kk + 4) * PK + row0 + 8]);
    }
    __syncthreads();  // QPs now reusable as Ps

    float m0 = -INFINITY, m1 = -INFINITY, ls0 = 0.f, ls1 = 0.f;
    float o[8][4];
    #pragma unroll
    for (int nt = 0; nt < 8; nt++)
        #pragma unroll
        for (int c = 0; c < 4; c++) o[nt][c] = 0.f;

    for (int jt = 0; jt < LL / 64; jt++) {
        int lk = jt << 6;
        __syncthreads();  // previous iteration's PV reads of Ks/Vs/Ps done

        // ---- load K,V tiles (tf32-convert into smem) ----
        #pragma unroll
        for (int r = 0; r < 8; r++) {
            int idx = r * 512 + tid * 4;
            int d = idx >> 6, j = idx & 63;
            float4 xk = *reinterpret_cast<const float4*>(&kb[(size_t)d * LL + lk + j]);
            Ks[d * PK + j + 0] = __uint_as_float(f2tf(xk.x));
            Ks[d * PK + j + 1] = __uint_as_float(f2tf(xk.y));
            Ks[d * PK + j + 2] = __uint_as_float(f2tf(xk.z));
            Ks[d * PK + j + 3] = __uint_as_float(f2tf(xk.w));
            float4 xv = *reinterpret_cast<const float4*>(&vb[(size_t)d * LL + lk + j]);
            Vs[d * PV + j + 0] = __uint_as_float(f2tf(xv.x));
            Vs[d * PV + j + 1] = __uint_as_float(f2tf(xv.y));
            Vs[d * PV + j + 2] = __uint_as_float(f2tf(xv.z));
            Vs[d * PV + j + 3] = __uint_as_float(f2tf(xv.w));
        }
        __syncthreads();

        // ---- S = Q K^T  (B[k=d][n=j] = K[j][d] = Ks[d][j]) ----
        float s[8][4];
        #pragma unroll
        for (int nt = 0; nt < 8; nt++)
            #pragma unroll
            for (int c = 0; c < 4; c++) s[nt][c] = 0.f;
        #pragma unroll
        for (int kt = 0; kt < 8; kt++) {
            int kk = kt * 8;
            #pragma unroll
            for (int nt = 0; nt < 8; nt++) {
                unsigned b0 = __float_as_uint(Ks[(kk + t4) * PK + nt * 8 + g]);
                unsigned b1 = __float_as_uint(Ks[(kk + t4 + 4) * PK + nt * 8 + g]);
                mma_tf32(s[nt], qa[kt], b0, b1);
            }
        }

        // ---- online softmax (base-2; scale folded into Q) ----
        float mx0 = -INFINITY, mx1 = -INFINITY;
        #pragma unroll
        for (int nt = 0; nt < 8; nt++) {
            mx0 = fmaxf(mx0, fmaxf(s[nt][0], s[nt][1]));
            mx1 = fmaxf(mx1, fmaxf(s[nt][2], s[nt][3]));
        }
        mx0 = fmaxf(mx0, __shfl_xor_sync(0xffffffffu, mx0, 1));
        mx0 = fmaxf(mx0, __shfl_xor_sync(0xffffffffu, mx0, 2));
        mx1 = fmaxf(mx1, __shfl_xor_sync(0xffffffffu, mx1, 1));
        mx1 = fmaxf(mx1, __shfl_xor_sync(0xffffffffu, mx1, 2));
        float mn0 = fmaxf(m0, mx0), mn1 = fmaxf(m1, mx1);
        float c0 = ex2f(m0 - mn0), c1 = ex2f(m1 - mn1);
        float rs0 = 0.f, rs1 = 0.f;
        float* Ps = QPs;
        #pragma unroll
        for (int nt = 0; nt < 8; nt++) {
            float p00 = ex2f(s[nt][0] - mn0);
            float p01 = ex2f(s[nt][1] - mn0);
            float p10 = ex2f(s[nt][2] - mn1);
            float p11 = ex2f(s[nt][3] - mn1);
            rs0 += p00 + p01;
            rs1 += p10 + p11;
            int colc = nt * 8 + 2 * t4;
            float2 w0 = make_float2(__uint_as_float(f2tf(p00)), __uint_as_float(f2tf(p01)));
            float2 w1 = make_float2(__uint_as_float(f2tf(p10)), __uint_as_float(f2tf(p11)));
            *reinterpret_cast<float2*>(&Ps[row0 * PP + colc])       = w0;
            *reinterpret_cast<float2*>(&Ps[(row0 + 8) * PP + colc]) = w1;
        }
        rs0 += __shfl_xor_sync(0xffffffffu, rs0, 1);
        rs0 += __shfl_xor_sync(0xffffffffu, rs0, 2);
        rs1 += __shfl_xor_sync(0xffffffffu, rs1, 1);
        rs1 += __shfl_xor_sync(0xffffffffu, rs1, 2);
        ls0 = ls0 * c0 + rs0;
        ls1 = ls1 * c1 + rs1;
        m0 = mn0; m1 = mn1;
        #pragma unroll
        for (int nt = 0; nt < 8; nt++) {
            o[nt][0] *= c0; o[nt][1] *= c0;
            o[nt][2] *= c1; o[nt][3] *= c1;
        }
        __syncwarp();  // Ps rows of this warp visible to whole warp

        // ---- O += P V  (A = P[i][j], B[k=j][n=d] = V[j][d] = Vs[d][j]) ----
        #pragma unroll
        for (int kt = 0; kt < 8; kt++) {
            int kk = kt * 8;
            unsigned a[4];
            a[0] = __float_as_uint(Ps[row0 * PP + kk + t4]);
            a[1] = __float_as_uint(Ps[(row0 + 8) * PP + kk + t4]);
            a[2] = __float_as_uint(Ps[row0 * PP + kk + t4 + 4]);
            a[3] = __float_as_uint(Ps[(row0 + 8) * PP + kk + t4 + 4]);
            #pragma unroll
            for (int nt = 0; nt < 8; nt++) {
                unsigned b0 = __float_as_uint(Vs[(nt * 8 + g) * PV + kk + t4]);
                unsigned b1 = __float_as_uint(Vs[(nt * 8 + g) * PV + kk + t4 + 4]);
                mma_tf32(o[nt], a, b0, b1);
            }
        }
    }

    // ---- normalize, stage O^T into smem (Ks reused, [d][i] pad PV), write ----
    __syncthreads();  // all warps done reading Ks/Vs
    float inv0 = 1.f / ls0, inv1 = 1.f / ls1;
    float* Os = Ks;
    #pragma unroll
    for (int nt = 0; nt < 8; nt++) {
        int d = nt * 8 + 2 * t4;
        Os[(d    ) * PV + row0]     = o[nt][0] * inv0;
        Os[(d + 1) * PV + row0]     = o[nt][1] * inv0;
        Os[(d    ) * PV + row0 + 8] = o[nt][2] * inv1;
        Os[(d + 1) * PV + row0 + 8] = o[nt][3] * inv1;
    }
    __syncthreads();
    const size_t cbase = (size_t)n * CC + h * DH;
    #pragma unroll
    for (int r = 0; r < 8; r++) {
        int idx = r * 512 + tid * 4;
        int d = idx >> 6, i = idx & 63;
        float4 val = *reinterpret_cast<const float4*>(&Os[d * PV + i]);
        *reinterpret_cast<float4*>(&ao[(cbase + d) * LL + l0 + i]) = val;
    }
}

// ---------------------------------------------------------------------------
extern "C" void kernel_launch(void* const* d_in, const int* in_sizes, int n_in,
                              void* d_out, int out_size) {
    const float* x     = (const float*)d_in[0];
    const float* gamma = (const float*)d_in[1];
    const float* beta  = (const float*)d_in[2];
    const float* Wq    = (const float*)d_in[3];
    const float* Wk    = (const float*)d_in[4];
    const float* Wv    = (const float*)d_in[5];
    const float* Wp    = (const float*)d_in[6];
    const float* bp    = (const float*)d_in[7];
    float* out = (float*)d_out;

    float *xn, *q, *k, *v, *ao;
    cudaGetSymbolAddress((void**)&xn, g_xn);
    cudaGetSymbolAddress((void**)&q,  g_q);
    cudaGetSymbolAddress((void**)&k,  g_k);
    cudaGetSymbolAddress((void**)&v,  g_v);
    cudaGetSymbolAddress((void**)&ao, g_ao);

    // GroupNorm
    gn_kernel<<<NB * GROUPS, 256>>>(x, gamma, beta, xn);

    // Q/K/V projections
    dim3 pgrid(LL / 64, CC / 64, NB), pblk(16, 16);
    proj_kernel<<<pgrid, pblk>>>(Wq, xn, nullptr, q);
    proj_kernel<<<pgrid, pblk>>>(Wk, xn, nullptr, k);
    proj_kernel<<<pgrid, pblk>>>(Wv, xn, nullptr, v);

    // Flash attention (tensor cores, tf32)
    size_t smem = (size_t)(64 * PK + 64 * PV + 64 * PK) * sizeof(float);  // 54272 B
    cudaFuncSetAttribute(attn_tc_kernel, cudaFuncAttributeMaxDynamicSharedMemorySize, (int)smem);
    attn_tc_kernel<<<dim3(LL / 64, NB * HEADS), 128, smem>>>(q, k, v, ao);

    // Output projection (+bias) straight into d_out
    proj_kernel<<<pgrid, pblk>>>(Wp, ao, bp, out);
}

// round 4
// speedup vs baseline: 3.0289x; 1.2540x over previous
#include <cuda_runtime.h>
#include <math.h>

#define NB 4
#define CC 256
#define HEADS 4
#define DH 64
#define LL 4096
#define GROUPS 32

// Scratch (allocation-free rule: __device__ globals)
__device__ float g_xn[NB * CC * LL];
__device__ float g_q [NB * CC * LL];
__device__ float g_k [NB * CC * LL];
__device__ float g_v [NB * CC * LL];
__device__ float g_ao[NB * CC * LL];
__device__ float g_wt[4 * CC * CC];   // tf32-rounded Wq,Wk,Wv,Wp

// ---------------------------------------------------------------------------
// helpers
// ---------------------------------------------------------------------------
__device__ __forceinline__ unsigned f2tf(float x) {
    unsigned u;
    asm("cvt.rna.tf32.f32 %0, %1;" : "=r"(u) : "f"(x));
    return u;
}
__device__ __forceinline__ float f2tff(float x) { return __uint_as_float(f2tf(x)); }
__device__ __forceinline__ float ex2f(float x) {
    float r;
    asm("ex2.approx.ftz.f32 %0, %1;" : "=f"(r) : "f"(x));
    return r;
}
__device__ __forceinline__ void mma_tf32(float* c, const unsigned* a,
                                         unsigned b0, unsigned b1) {
    asm volatile(
        "mma.sync.aligned.m16n8k8.row.col.f32.tf32.tf32.f32 "
        "{%0,%1,%2,%3}, {%4,%5,%6,%7}, {%8,%9}, {%0,%1,%2,%3};"
        : "+f"(c[0]), "+f"(c[1]), "+f"(c[2]), "+f"(c[3])
        : "r"(a[0]), "r"(a[1]), "r"(a[2]), "r"(a[3]), "r"(b0), "r"(b1));
}

// ---------------------------------------------------------------------------
// Weight prep: round all 4 weight matrices to tf32 (cvt.rna) once per launch.
// ---------------------------------------------------------------------------
__global__ void wcvt_kernel(const float* __restrict__ Wq, const float* __restrict__ Wk,
                            const float* __restrict__ Wv, const float* __restrict__ Wp,
                            float* __restrict__ wt) {
    int i4 = (blockIdx.x * 256 + threadIdx.x) * 4;
    const float* src[4] = {Wq, Wk, Wv, Wp};
    #pragma unroll
    for (int m = 0; m < 4; m++) {
        float4 w = *reinterpret_cast<const float4*>(&src[m][i4]);
        float4 r = make_float4(f2tff(w.x), f2tff(w.y), f2tff(w.z), f2tff(w.w));
        *reinterpret_cast<float4*>(&wt[m * CC * CC + i4]) = r;
    }
}

// ---------------------------------------------------------------------------
// GroupNorm: one block per (n, group). Output tf32-rounded (feeds tf32 GEMM).
// ---------------------------------------------------------------------------
__global__ void gn_kernel(const float* __restrict__ x,
                          const float* __restrict__ gamma,
                          const float* __restrict__ beta,
                          float* __restrict__ xn) {
    int n = blockIdx.x >> 5;
    int g = blockIdx.x & 31;
    const float* xp = x  + (size_t)(n * CC + g * 8) * LL;
    float*       op = xn + (size_t)(n * CC + g * 8) * LL;

    float s = 0.f, ss = 0.f;
    for (int i = threadIdx.x; i < 8 * LL; i += 256) {
        float v = xp[i];
        s += v; ss += v * v;
    }
    __shared__ float rs[256], rss[256];
    rs[threadIdx.x] = s; rss[threadIdx.x] = ss;
    __syncthreads();
    for (int o = 128; o > 0; o >>= 1) {
        if (threadIdx.x < o) {
            rs[threadIdx.x]  += rs[threadIdx.x + o];
            rss[threadIdx.x] += rss[threadIdx.x + o];
        }
        __syncthreads();
    }
    const float invN = 1.f / (8.f * LL);
    float mean = rs[0] * invN;
    float var  = rss[0] * invN - mean * mean;
    float inv  = rsqrtf(var + 1e-5f);
    for (int i = threadIdx.x; i < 8 * LL; i += 256) {
        int c = g * 8 + (i >> 12);
        op[i] = f2tff((xp[i] - mean) * inv * gamma[c] + beta[c]);
    }
}

// ---------------------------------------------------------------------------
// Fused QKV projection on tensor cores (tf32).
// Block: 128 thr, tile 64(o) x 64(l), K=256 in 32-chunks; 3 weight sets share X.
// Xs pad 72 (B-frag banks 8*t4+g), Ws pad 40 (A-frag banks 8*g+t4): conflict-free.
// ---------------------------------------------------------------------------
__global__ void __launch_bounds__(128) qkv_tc_kernel(
        const float* __restrict__ xn, const float* __restrict__ wt,
        float* __restrict__ q, float* __restrict__ k, float* __restrict__ v) {
    __shared__ float Xs[32 * 72];
    __shared__ float Ws[3][64 * 40];

    int n  = blockIdx.z;
    int o0 = blockIdx.y << 6;
    int l0 = blockIdx.x << 6;
    const float* xb = xn + (size_t)n * CC * LL;

    int tid = threadIdx.x;
    int lane = tid & 31, w = tid >> 5;
    int g = lane >> 2, t4 = lane & 3;

    float acc[3][8][4];
    #pragma unroll
    for (int m = 0; m < 3; m++)
        #pragma unroll
        for (int nt = 0; nt < 8; nt++)
            #pragma unroll
            for (int c = 0; c < 4; c++) acc[m][nt][c] = 0.f;

    for (int c0 = 0; c0 < CC; c0 += 32) {
        __syncthreads();
        // X tile [c][l]
        #pragma unroll
        for (int r = 0; r < 4; r++) {
            int idx = r * 512 + tid * 4;
            int cc = idx >> 6, ll = idx & 63;
            float4 xv = *reinterpret_cast<const float4*>(&xb[(size_t)(c0 + cc) * LL + l0 + ll]);
            *reinterpret_cast<float4*>(&Xs[cc * 72 + ll]) = xv;
        }
        // W tiles [o][c]
        #pragma unroll
        for (int m = 0; m < 3; m++) {
            const float* Wm = wt + m * CC * CC;
            #pragma unroll
            for (int p = 0; p < 4; p++) {
                int oo = (tid >> 3) + p * 16;
                int cc4 = (tid & 7) * 4;
                float4 wv = *reinterpret_cast<const float4*>(&Wm[(o0 + oo) * CC + c0 + cc4]);
                *reinterpret_cast<float4*>(&Ws[m][oo * 40 + cc4]) = wv;
            }
        }
        __syncthreads();

        #pragma unroll
        for (int kt = 0; kt < 4; kt++) {
            int kk = kt * 8;
            unsigned a[3][4];
            #pragma unroll
            for (int m = 0; m < 3; m++) {
                a[m][0] = __float_as_uint(Ws[m][(w * 16 + g) * 40 + kk + t4]);
                a[m][1] = __float_as_uint(Ws[m][(w * 16 + g + 8) * 40 + kk + t4]);
                a[m][2] = __float_as_uint(Ws[m][(w * 16 + g) * 40 + kk + t4 + 4]);
                a[m][3] = __float_as_uint(Ws[m][(w * 16 + g + 8) * 40 + kk + t4 + 4]);
            }
            #pragma unroll
            for (int nt = 0; nt < 8; nt++) {
                unsigned b0 = __float_as_uint(Xs[(kk + t4) * 72 + nt * 8 + g]);
                unsigned b1 = __float_as_uint(Xs[(kk + t4 + 4) * 72 + nt * 8 + g]);
                mma_tf32(acc[0][nt], a[0], b0, b1);
                mma_tf32(acc[1][nt], a[1], b0, b1);
                mma_tf32(acc[2][nt], a[2], b0, b1);
            }
        }
    }

    float* outs[3] = {q, k, v};
    int orow = o0 + w * 16 + g;
    #pragma unroll
    for (int m = 0; m < 3; m++) {
        float* op = outs[m] + (size_t)n * CC * LL;
        #pragma unroll
        for (int nt = 0; nt < 8; nt++) {
            size_t base = (size_t)orow * LL + l0 + nt * 8 + 2 * t4;
            *reinterpret_cast<float2*>(&op[base]) =
                make_float2(acc[m][nt][0], acc[m][nt][1]);
            *reinterpret_cast<float2*>(&op[base + 8 * LL]) =
                make_float2(acc[m][nt][2], acc[m][nt][3]);
        }
    }
}

// ---------------------------------------------------------------------------
// Output projection on tensor cores (tf32) + bias, writes d_out.
// ---------------------------------------------------------------------------
__global__ void __launch_bounds__(128) oproj_tc_kernel(
        const float* __restrict__ ao, const float* __restrict__ wt,
        const float* __restrict__ bias, float* __restrict__ out) {
    __shared__ float Xs[32 * 72];
    __shared__ float Ws[64 * 40];

    int n  = blockIdx.z;
    int o0 = blockIdx.y << 6;
    int l0 = blockIdx.x << 6;
    const float* xb = ao + (size_t)n * CC * LL;

    int tid = threadIdx.x;
    int lane = tid & 31, w = tid >> 5;
    int g = lane >> 2, t4 = lane & 3;

    float acc[8][4];
    #pragma unroll
    for (int nt = 0; nt < 8; nt++)
        #pragma unroll
        for (int c = 0; c < 4; c++) acc[nt][c] = 0.f;

    for (int c0 = 0; c0 < CC; c0 += 32) {
        __syncthreads();
        #pragma unroll
        for (int r = 0; r < 4; r++) {
            int idx = r * 512 + tid * 4;
            int cc = idx >> 6, ll = idx & 63;
            float4 xv = *reinterpret_cast<const float4*>(&xb[(size_t)(c0 + cc) * LL + l0 + ll]);
            *reinterpret_cast<float4*>(&Xs[cc * 72 + ll]) = xv;
        }
        #pragma unroll
        for (int p = 0; p < 4; p++) {
            int oo = (tid >> 3) + p * 16;
            int cc4 = (tid & 7) * 4;
            float4 wv = *reinterpret_cast<const float4*>(&wt[(o0 + oo) * CC + c0 + cc4]);
            *reinterpret_cast<float4*>(&Ws[oo * 40 + cc4]) = wv;
        }
        __syncthreads();

        #pragma unroll
        for (int kt = 0; kt < 4; kt++) {
            int kk = kt * 8;
            unsigned a[4];
            a[0] = __float_as_uint(Ws[(w * 16 + g) * 40 + kk + t4]);
            a[1] = __float_as_uint(Ws[(w * 16 + g + 8) * 40 + kk + t4]);
            a[2] = __float_as_uint(Ws[(w * 16 + g) * 40 + kk + t4 + 4]);
            a[3] = __float_as_uint(Ws[(w * 16 + g + 8) * 40 + kk + t4 + 4]);
            #pragma unroll
            for (int nt = 0; nt < 8; nt++) {
                unsigned b0 = __float_as_uint(Xs[(kk + t4) * 72 + nt * 8 + g]);
                unsigned b1 = __float_as_uint(Xs[(kk + t4 + 4) * 72 + nt * 8 + g]);
                mma_tf32(acc[nt], a, b0, b1);
            }
        }
    }

    int orow = o0 + w * 16 + g;
    float bb0 = bias[orow], bb1 = bias[orow + 8];
    float* op = out + (size_t)n * CC * LL;
    #pragma unroll
    for (int nt = 0; nt < 8; nt++) {
        size_t base = (size_t)orow * LL + l0 + nt * 8 + 2 * t4;
        *reinterpret_cast<float2*>(&op[base]) =
            make_float2(acc[nt][0] + bb0, acc[nt][1] + bb0);
        *reinterpret_cast<float2*>(&op[base + 8 * LL]) =
            make_float2(acc[nt][2] + bb1, acc[nt][3] + bb1);
    }
}

// ---------------------------------------------------------------------------
// Flash attention on tensor cores (tf32 mma.sync m16n8k8). Same as the 822us
// passing version, except the epilogue rounds O to tf32.
// ---------------------------------------------------------------------------
#define PK 72
#define PV 68
#define PP 68

__global__ void attn_tc_kernel(const float* __restrict__ q,
                               const float* __restrict__ k,
                               const float* __restrict__ v,
                               float* __restrict__ ao) {
    extern __shared__ float sm[];
    float* Ks  = sm;
    float* Vs  = sm + 64 * PK;
    float* QPs = Vs + 64 * PV;

    int nh = blockIdx.y;
    int n = nh >> 2, h = nh & 3;
    int l0 = blockIdx.x << 6;
    const float* qb = q + ((size_t)n * CC + h * DH) * LL;
    const float* kb = k + ((size_t)n * CC + h * DH) * LL;
    const float* vb = v + ((size_t)n * CC + h * DH) * LL;

    int tid  = threadIdx.x;
    int lane = tid & 31, w = tid >> 5;
    int g = lane >> 2, t4 = lane & 3;
    int row0 = w * 16 + g;

    const float qscale = 0.125f * 1.44269504088896340736f;

    #pragma unroll
    for (int r = 0; r < 8; r++) {
        int idx = r * 512 + tid * 4;
        int d = idx >> 6, j = idx & 63;
        float4 xq = *reinterpret_cast<const float4*>(&qb[(size_t)d * LL + l0 + j]);
        QPs[d * PK + j + 0] = f2tff(xq.x * qscale);
        QPs[d * PK + j + 1] = f2tff(xq.y * qscale);
        QPs[d * PK + j + 2] = f2tff(xq.z * qscale);
        QPs[d * PK + j + 3] = f2tff(xq.w * qscale);
    }
    __syncthreads();

    unsigned qa[8][4];
    #pragma unroll
    for (int kt = 0; kt < 8; kt++) {
        int kk = kt * 8 + t4;
        qa[kt][0] = __float_as_uint(QPs[kk * PK + row0]);
        qa[kt][1] = __float_as_uint(QPs[kk * PK + row0 + 8]);
        qa[kt][2] = __float_as_uint(QPs[(kk + 4) * PK + row0]);
        qa[kt][3] = __float_as_uint(QPs[(kk + 4) * PK + row0 + 8]);
    }
    __syncthreads();

    float m0 = -INFINITY, m1 = -INFINITY, ls0 = 0.f, ls1 = 0.f;
    float o[8][4];
    #pragma unroll
    for (int nt = 0; nt < 8; nt++)
        #pragma unroll
        for (int c = 0; c < 4; c++) o[nt][c] = 0.f;

    for (int jt = 0; jt < LL / 64; jt++) {
        int lk = jt << 6;
        __syncthreads();

        #pragma unroll
        for (int r = 0; r < 8; r++) {
            int idx = r * 512 + tid * 4;
            int d = idx >> 6, j = idx & 63;
            float4 xk = *reinterpret_cast<const float4*>(&kb[(size_t)d * LL + lk + j]);
            Ks[d * PK + j + 0] = f2tff(xk.x);
            Ks[d * PK + j + 1] = f2tff(xk.y);
            Ks[d * PK + j + 2] = f2tff(xk.z);
            Ks[d * PK + j + 3] = f2tff(xk.w);
            float4 xv = *reinterpret_cast<const float4*>(&vb[(size_t)d * LL + lk + j]);
            Vs[d * PV + j + 0] = f2tff(xv.x);
            Vs[d * PV + j + 1] = f2tff(xv.y);
            Vs[d * PV + j + 2] = f2tff(xv.z);
            Vs[d * PV + j + 3] = f2tff(xv.w);
        }
        __syncthreads();

        float s[8][4];
        #pragma unroll
        for (int nt = 0; nt < 8; nt++)
            #pragma unroll
            for (int c = 0; c < 4; c++) s[nt][c] = 0.f;
        #pragma unroll
        for (int kt = 0; kt < 8; kt++) {
            int kk = kt * 8;
            #pragma unroll
            for (int nt = 0; nt < 8; nt++) {
                unsigned b0 = __float_as_uint(Ks[(kk + t4) * PK + nt * 8 + g]);
                unsigned b1 = __float_as_uint(Ks[(kk + t4 + 4) * PK + nt * 8 + g]);
                mma_tf32(s[nt], qa[kt], b0, b1);
            }
        }

        float mx0 = -INFINITY, mx1 = -INFINITY;
        #pragma unroll
        for (int nt = 0; nt < 8; nt++) {
            mx0 = fmaxf(mx0, fmaxf(s[nt][0], s[nt][1]));
            mx1 = fmaxf(mx1, fmaxf(s[nt][2], s[nt][3]));
        }
        mx0 = fmaxf(mx0, __shfl_xor_sync(0xffffffffu, mx0, 1));
        mx0 = fmaxf(mx0, __shfl_xor_sync(0xffffffffu, mx0, 2));
        mx1 = fmaxf(mx1, __shfl_xor_sync(0xffffffffu, mx1, 1));
        mx1 = fmaxf(mx1, __shfl_xor_sync(0xffffffffu, mx1, 2));
        float mn0 = fmaxf(m0, mx0), mn1 = fmaxf(m1, mx1);
        float c0 = ex2f(m0 - mn0), c1 = ex2f(m1 - mn1);
        float rs0 = 0.f, rs1 = 0.f;
        float* Ps = QPs;
        #pragma unroll
        for (int nt = 0; nt < 8; nt++) {
            float p00 = ex2f(s[nt][0] - mn0);
            float p01 = ex2f(s[nt][1] - mn0);
            float p10 = ex2f(s[nt][2] - mn1);
            float p11 = ex2f(s[nt][3] - mn1);
            rs0 += p00 + p01;
            rs1 += p10 + p11;
            int colc = nt * 8 + 2 * t4;
            float2 w0 = make_float2(f2tff(p00), f2tff(p01));
            float2 w1 = make_float2(f2tff(p10), f2tff(p11));
            *reinterpret_cast<float2*>(&Ps[row0 * PP + colc])       = w0;
            *reinterpret_cast<float2*>(&Ps[(row0 + 8) * PP + colc]) = w1;
        }
        rs0 += __shfl_xor_sync(0xffffffffu, rs0, 1);
        rs0 += __shfl_xor_sync(0xffffffffu, rs0, 2);
        rs1 += __shfl_xor_sync(0xffffffffu, rs1, 1);
        rs1 += __shfl_xor_sync(0xffffffffu, rs1, 2);
        ls0 = ls0 * c0 + rs0;
        ls1 = ls1 * c1 + rs1;
        m0 = mn0; m1 = mn1;
        #pragma unroll
        for (int nt = 0; nt < 8; nt++) {
            o[nt][0] *= c0; o[nt][1] *= c0;
            o[nt][2] *= c1; o[nt][3] *= c1;
        }
        __syncwarp();

        #pragma unroll
        for (int kt = 0; kt < 8; kt++) {
            int kk = kt * 8;
            unsigned a[4];
            a[0] = __float_as_uint(Ps[row0 * PP + kk + t4]);
            a[1] = __float_as_uint(Ps[(row0 + 8) * PP + kk + t4]);
            a[2] = __float_as_uint(Ps[row0 * PP + kk + t4 + 4]);
            a[3] = __float_as_uint(Ps[(row0 + 8) * PP + kk + t4 + 4]);
            #pragma unroll
            for (int nt = 0; nt < 8; nt++) {
                unsigned b0 = __float_as_uint(Vs[(nt * 8 + g) * PV + kk + t4]);
                unsigned b1 = __float_as_uint(Vs[(nt * 8 + g) * PV + kk + t4 + 4]);
                mma_tf32(o[nt], a, b0, b1);
            }
        }
    }

    __syncthreads();
    float inv0 = 1.f / ls0, inv1 = 1.f / ls1;
    float* Os = Ks;
    #pragma unroll
    for (int nt = 0; nt < 8; nt++) {
        int d = nt * 8 + 2 * t4;
        Os[(d    ) * PV + row0]     = f2tff(o[nt][0] * inv0);
        Os[(d + 1) * PV + row0]     = f2tff(o[nt][1] * inv0);
        Os[(d    ) * PV + row0 + 8] = f2tff(o[nt][2] * inv1);
        Os[(d + 1) * PV + row0 + 8] = f2tff(o[nt][3] * inv1);
    }
    __syncthreads();
    const size_t cbase = (size_t)n * CC + h * DH;
    #pragma unroll
    for (int r = 0; r < 8; r++) {
        int idx = r * 512 + tid * 4;
        int d = idx >> 6, i = idx & 63;
        float4 val = *reinterpret_cast<const float4*>(&Os[d * PV + i]);
        *reinterpret_cast<float4*>(&ao[(cbase + d) * LL + l0 + i]) = val;
    }
}

// ---------------------------------------------------------------------------
extern "C" void kernel_launch(void* const* d_in, const int* in_sizes, int n_in,
                              void* d_out, int out_size) {
    const float* x     = (const float*)d_in[0];
    const float* gamma = (const float*)d_in[1];
    const float* beta  = (const float*)d_in[2];
    const float* Wq    = (const float*)d_in[3];
    const float* Wk    = (const float*)d_in[4];
    const float* Wv    = (const float*)d_in[5];
    const float* Wp    = (const float*)d_in[6];
    const float* bp    = (const float*)d_in[7];
    float* out = (float*)d_out;

    // One-time scratch address lookup + smem attr set (deterministic, cached)
    static float *xn = nullptr, *q, *k, *v, *ao, *wt;
    static size_t attn_smem = (size_t)(64 * PK + 64 * PV + 64 * PK) * sizeof(float);
    if (!xn) {
        cudaGetSymbolAddress((void**)&xn, g_xn);
        cudaGetSymbolAddress((void**)&q,  g_q);
        cudaGetSymbolAddress((void**)&k,  g_k);
        cudaGetSymbolAddress((void**)&v,  g_v);
        cudaGetSymbolAddress((void**)&ao, g_ao);
        cudaGetSymbolAddress((void**)&wt, g_wt);
        cudaFuncSetAttribute(attn_tc_kernel,
                             cudaFuncAttributeMaxDynamicSharedMemorySize,
                             (int)attn_smem);
    }

    // Weight tf32 prep + GroupNorm (independent)
    wcvt_kernel<<<CC * CC / (256 * 4), 256>>>(Wq, Wk, Wv, Wp, wt);
    gn_kernel<<<NB * GROUPS, 256>>>(x, gamma, beta, xn);

    // Fused QKV projection (tensor cores)
    dim3 pgrid(LL / 64, CC / 64, NB);
    qkv_tc_kernel<<<pgrid, 128>>>(xn, wt, q, k, v);

    // Flash attention (tensor cores, tf32)
    attn_tc_kernel<<<dim3(LL / 64, NB * HEADS), 128, attn_smem>>>(q, k, v, ao);

    // Output projection (+bias) straight into d_out (tensor cores)
    oproj_tc_kernel<<<pgrid, 128>>>(ao, wt + 3 * CC * CC, bp, out);
}

// round 5
// speedup vs baseline: 3.0672x; 1.0127x over previous
#include <cuda_runtime.h>
#include <math.h>

#define NB 4
#define CC 256
#define HEADS 4
#define DH 64
#define LL 4096
#define GROUPS 32

// Scratch (allocation-free rule: __device__ globals)
__device__ float g_xn[NB * CC * LL];
__device__ float g_q [NB * CC * LL];
__device__ float g_k [NB * CC * LL];
__device__ float g_v [NB * CC * LL];
__device__ float g_ao[NB * CC * LL];
__device__ float g_wt[4 * CC * CC];   // tf32-rounded Wq,Wk,Wv,Wp

// ---------------------------------------------------------------------------
// helpers
// ---------------------------------------------------------------------------
__device__ __forceinline__ unsigned f2tf(float x) {
    unsigned u;
    asm("cvt.rna.tf32.f32 %0, %1;" : "=r"(u) : "f"(x));
    return u;
}
__device__ __forceinline__ float f2tff(float x) { return __uint_as_float(f2tf(x)); }
__device__ __forceinline__ float ex2f(float x) {
    float r;
    asm("ex2.approx.ftz.f32 %0, %1;" : "=f"(r) : "f"(x));
    return r;
}
__device__ __forceinline__ void mma_tf32(float* c, const unsigned* a,
                                         unsigned b0, unsigned b1) {
    asm volatile(
        "mma.sync.aligned.m16n8k8.row.col.f32.tf32.tf32.f32 "
        "{%0,%1,%2,%3}, {%4,%5,%6,%7}, {%8,%9}, {%0,%1,%2,%3};"
        : "+f"(c[0]), "+f"(c[1]), "+f"(c[2]), "+f"(c[3])
        : "r"(a[0]), "r"(a[1]), "r"(a[2]), "r"(a[3]), "r"(b0), "r"(b1));
}

// ---------------------------------------------------------------------------
// Weight prep: round all 4 weight matrices to tf32 (cvt.rna) once per launch.
// ---------------------------------------------------------------------------
__global__ void wcvt_kernel(const float* __restrict__ Wq, const float* __restrict__ Wk,
                            const float* __restrict__ Wv, const float* __restrict__ Wp,
                            float* __restrict__ wt) {
    int i4 = (blockIdx.x * 256 + threadIdx.x) * 4;
    const float* src[4] = {Wq, Wk, Wv, Wp};
    #pragma unroll
    for (int m = 0; m < 4; m++) {
        float4 w = *reinterpret_cast<const float4*>(&src[m][i4]);
        float4 r = make_float4(f2tff(w.x), f2tff(w.y), f2tff(w.z), f2tff(w.w));
        *reinterpret_cast<float4*>(&wt[m * CC * CC + i4]) = r;
    }
}

// ---------------------------------------------------------------------------
// GroupNorm: one block per (n, group). Output tf32-rounded (feeds tf32 GEMM).
// ---------------------------------------------------------------------------
__global__ void gn_kernel(const float* __restrict__ x,
                          const float* __restrict__ gamma,
                          const float* __restrict__ beta,
                          float* __restrict__ xn) {
    int n = blockIdx.x >> 5;
    int g = blockIdx.x & 31;
    const float* xp = x  + (size_t)(n * CC + g * 8) * LL;
    float*       op = xn + (size_t)(n * CC + g * 8) * LL;

    float s = 0.f, ss = 0.f;
    for (int i = threadIdx.x; i < 8 * LL; i += 256) {
        float v = xp[i];
        s += v; ss += v * v;
    }
    __shared__ float rs[256], rss[256];
    rs[threadIdx.x] = s; rss[threadIdx.x] = ss;
    __syncthreads();
    for (int o = 128; o > 0; o >>= 1) {
        if (threadIdx.x < o) {
            rs[threadIdx.x]  += rs[threadIdx.x + o];
            rss[threadIdx.x] += rss[threadIdx.x + o];
        }
        __syncthreads();
    }
    const float invN = 1.f / (8.f * LL);
    float mean = rs[0] * invN;
    float var  = rss[0] * invN - mean * mean;
    float inv  = rsqrtf(var + 1e-5f);
    for (int i = threadIdx.x; i < 8 * LL; i += 256) {
        int c = g * 8 + (i >> 12);
        op[i] = f2tff((xp[i] - mean) * inv * gamma[c] + beta[c]);
    }
}

// ---------------------------------------------------------------------------
// Fused QKV projection on tensor cores (tf32). (unchanged from R4)
// ---------------------------------------------------------------------------
__global__ void __launch_bounds__(128) qkv_tc_kernel(
        const float* __restrict__ xn, const float* __restrict__ wt,
        float* __restrict__ q, float* __restrict__ k, float* __restrict__ v) {
    __shared__ float Xs[32 * 72];
    __shared__ float Ws[3][64 * 40];

    int n  = blockIdx.z;
    int o0 = blockIdx.y << 6;
    int l0 = blockIdx.x << 6;
    const float* xb = xn + (size_t)n * CC * LL;

    int tid = threadIdx.x;
    int lane = tid & 31, w = tid >> 5;
    int g = lane >> 2, t4 = lane & 3;

    float acc[3][8][4];
    #pragma unroll
    for (int m = 0; m < 3; m++)
        #pragma unroll
        for (int nt = 0; nt < 8; nt++)
            #pragma unroll
            for (int c = 0; c < 4; c++) acc[m][nt][c] = 0.f;

    for (int c0 = 0; c0 < CC; c0 += 32) {
        __syncthreads();
        #pragma unroll
        for (int r = 0; r < 4; r++) {
            int idx = r * 512 + tid * 4;
            int cc = idx >> 6, ll = idx & 63;
            float4 xv = *reinterpret_cast<const float4*>(&xb[(size_t)(c0 + cc) * LL + l0 + ll]);
            *reinterpret_cast<float4*>(&Xs[cc * 72 + ll]) = xv;
        }
        #pragma unroll
        for (int m = 0; m < 3; m++) {
            const float* Wm = wt + m * CC * CC;
            #pragma unroll
            for (int p = 0; p < 4; p++) {
                int oo = (tid >> 3) + p * 16;
                int cc4 = (tid & 7) * 4;
                float4 wv = *reinterpret_cast<const float4*>(&Wm[(o0 + oo) * CC + c0 + cc4]);
                *reinterpret_cast<float4*>(&Ws[m][oo * 40 + cc4]) = wv;
            }
        }
        __syncthreads();

        #pragma unroll
        for (int kt = 0; kt < 4; kt++) {
            int kk = kt * 8;
            unsigned a[3][4];
            #pragma unroll
            for (int m = 0; m < 3; m++) {
                a[m][0] = __float_as_uint(Ws[m][(w * 16 + g) * 40 + kk + t4]);
                a[m][1] = __float_as_uint(Ws[m][(w * 16 + g + 8) * 40 + kk + t4]);
                a[m][2] = __float_as_uint(Ws[m][(w * 16 + g) * 40 + kk + t4 + 4]);
                a[m][3] = __float_as_uint(Ws[m][(w * 16 + g + 8) * 40 + kk + t4 + 4]);
            }
            #pragma unroll
            for (int nt = 0; nt < 8; nt++) {
                unsigned b0 = __float_as_uint(Xs[(kk + t4) * 72 + nt * 8 + g]);
                unsigned b1 = __float_as_uint(Xs[(kk + t4 + 4) * 72 + nt * 8 + g]);
                mma_tf32(acc[0][nt], a[0], b0, b1);
                mma_tf32(acc[1][nt], a[1], b0, b1);
                mma_tf32(acc[2][nt], a[2], b0, b1);
            }
        }
    }

    float* outs[3] = {q, k, v};
    int orow = o0 + w * 16 + g;
    #pragma unroll
    for (int m = 0; m < 3; m++) {
        float* op = outs[m] + (size_t)n * CC * LL;
        #pragma unroll
        for (int nt = 0; nt < 8; nt++) {
            size_t base = (size_t)orow * LL + l0 + nt * 8 + 2 * t4;
            *reinterpret_cast<float2*>(&op[base]) =
                make_float2(acc[m][nt][0], acc[m][nt][1]);
            *reinterpret_cast<float2*>(&op[base + 8 * LL]) =
                make_float2(acc[m][nt][2], acc[m][nt][3]);
        }
    }
}

// ---------------------------------------------------------------------------
// Output projection on tensor cores (tf32) + bias, writes d_out. (unchanged)
// ---------------------------------------------------------------------------
__global__ void __launch_bounds__(128) oproj_tc_kernel(
        const float* __restrict__ ao, const float* __restrict__ wt,
        const float* __restrict__ bias, float* __restrict__ out) {
    __shared__ float Xs[32 * 72];
    __shared__ float Ws[64 * 40];

    int n  = blockIdx.z;
    int o0 = blockIdx.y << 6;
    int l0 = blockIdx.x << 6;
    const float* xb = ao + (size_t)n * CC * LL;

    int tid = threadIdx.x;
    int lane = tid & 31, w = tid >> 5;
    int g = lane >> 2, t4 = lane & 3;

    float acc[8][4];
    #pragma unroll
    for (int nt = 0; nt < 8; nt++)
        #pragma unroll
        for (int c = 0; c < 4; c++) acc[nt][c] = 0.f;

    for (int c0 = 0; c0 < CC; c0 += 32) {
        __syncthreads();
        #pragma unroll
        for (int r = 0; r < 4; r++) {
            int idx = r * 512 + tid * 4;
            int cc = idx >> 6, ll = idx & 63;
            float4 xv = *reinterpret_cast<const float4*>(&xb[(size_t)(c0 + cc) * LL + l0 + ll]);
            *reinterpret_cast<float4*>(&Xs[cc * 72 + ll]) = xv;
        }
        #pragma unroll
        for (int p = 0; p < 4; p++) {
            int oo = (tid >> 3) + p * 16;
            int cc4 = (tid & 7) * 4;
            float4 wv = *reinterpret_cast<const float4*>(&wt[(o0 + oo) * CC + c0 + cc4]);
            *reinterpret_cast<float4*>(&Ws[oo * 40 + cc4]) = wv;
        }
        __syncthreads();

        #pragma unroll
        for (int kt = 0; kt < 4; kt++) {
            int kk = kt * 8;
            unsigned a[4];
            a[0] = __float_as_uint(Ws[(w * 16 + g) * 40 + kk + t4]);
            a[1] = __float_as_uint(Ws[(w * 16 + g + 8) * 40 + kk + t4]);
            a[2] = __float_as_uint(Ws[(w * 16 + g) * 40 + kk + t4 + 4]);
            a[3] = __float_as_uint(Ws[(w * 16 + g + 8) * 40 + kk + t4 + 4]);
            #pragma unroll
            for (int nt = 0; nt < 8; nt++) {
                unsigned b0 = __float_as_uint(Xs[(kk + t4) * 72 + nt * 8 + g]);
                unsigned b1 = __float_as_uint(Xs[(kk + t4 + 4) * 72 + nt * 8 + g]);
                mma_tf32(acc[nt], a, b0, b1);
            }
        }
    }

    int orow = o0 + w * 16 + g;
    float bb0 = bias[orow], bb1 = bias[orow + 8];
    float* op = out + (size_t)n * CC * LL;
    #pragma unroll
    for (int nt = 0; nt < 8; nt++) {
        size_t base = (size_t)orow * LL + l0 + nt * 8 + 2 * t4;
        *reinterpret_cast<float2*>(&op[base]) =
            make_float2(acc[nt][0] + bb0, acc[nt][1] + bb0);
        *reinterpret_cast<float2*>(&op[base + 8 * LL]) =
            make_float2(acc[nt][2] + bb1, acc[nt][3] + bb1);
    }
}

// ---------------------------------------------------------------------------
// Flash attention, tf32 mma, warps tiled 2x2 over (m,n): each warp owns a
// 32-row x 32-col quarter => B-fragments reused across 2 m-tiles in registers
// (halves S-phase LDS). Softmax row stats combined across the 2 n-warps via
// a small smem stats array.
// ---------------------------------------------------------------------------
#define PK 72
#define PV 68
#define PP 68

__global__ void attn_tc_kernel(const float* __restrict__ q,
                               const float* __restrict__ k,
                               const float* __restrict__ v,
                               float* __restrict__ ao) {
    extern __shared__ float sm[];
    float* Ks    = sm;                       // [d][j] pad PK (also O^T staging)
    float* Vs    = sm + 64 * PK;             // [d][j] pad PV
    float* QPs   = Vs + 64 * PV;             // Q [d][i] pad PK, then P [i][j] pad PP
    float* stats = QPs + 64 * PK;            // [2][64] cross-warp row stats

    int nh = blockIdx.y;
    int n = nh >> 2, h = nh & 3;
    int l0 = blockIdx.x << 6;
    const float* qb = q + ((size_t)n * CC + h * DH) * LL;
    const float* kb = k + ((size_t)n * CC + h * DH) * LL;
    const float* vb = v + ((size_t)n * CC + h * DH) * LL;

    int tid  = threadIdx.x;
    int lane = tid & 31, w = tid >> 5;
    int wm = w >> 1, wn = w & 1;
    int g = lane >> 2, t4 = lane & 3;
    int rbase = wm * 32 + g;                 // + mt*16 (+8)

    const float qscale = 0.125f * 1.44269504088896340736f;

    // ---- load Q tile -> QPs[d][i] (pad PK), scaled + tf32 ----
    #pragma unroll
    for (int r = 0; r < 8; r++) {
        int idx = r * 512 + tid * 4;
        int d = idx >> 6, j = idx & 63;
        float4 xq = *reinterpret_cast<const float4*>(&qb[(size_t)d * LL + l0 + j]);
        QPs[d * PK + j + 0] = f2tff(xq.x * qscale);
        QPs[d * PK + j + 1] = f2tff(xq.y * qscale);
        QPs[d * PK + j + 2] = f2tff(xq.z * qscale);
        QPs[d * PK + j + 3] = f2tff(xq.w * qscale);
    }
    __syncthreads();

    // ---- Q fragments: qa[kt][mt][4] (64 regs) ----
    unsigned qa[8][2][4];
    #pragma unroll
    for (int kt = 0; kt < 8; kt++) {
        int k0 = kt * 8 + t4;
        #pragma unroll
        for (int mt = 0; mt < 2; mt++) {
            int row = rbase + mt * 16;
            qa[kt][mt][0] = __float_as_uint(QPs[k0 * PK + row]);
            qa[kt][mt][1] = __float_as_uint(QPs[k0 * PK + row + 8]);
            qa[kt][mt][2] = __float_as_uint(QPs[(k0 + 4) * PK + row]);
            qa[kt][mt][3] = __float_as_uint(QPs[(k0 + 4) * PK + row + 8]);
        }
    }
    __syncthreads();  // QPs now reusable as Ps

    float m[2][2], ls[2][2];
    #pragma unroll
    for (int mt = 0; mt < 2; mt++) {
        m[mt][0] = -INFINITY; m[mt][1] = -INFINITY;
        ls[mt][0] = 0.f; ls[mt][1] = 0.f;
    }
    float o[2][4][4];
    #pragma unroll
    for (int mt = 0; mt < 2; mt++)
        #pragma unroll
        for (int nt = 0; nt < 4; nt++)
            #pragma unroll
            for (int c = 0; c < 4; c++) o[mt][nt][c] = 0.f;

    for (int jt = 0; jt < LL / 64; jt++) {
        int lk = jt << 6;
        __syncthreads();  // previous tile's reads of Ks/Vs/Ps done

        // ---- load K,V tiles (tf32 into smem) ----
        #pragma unroll
        for (int r = 0; r < 8; r++) {
            int idx = r * 512 + tid * 4;
            int d = idx >> 6, j = idx & 63;
            float4 xk = *reinterpret_cast<const float4*>(&kb[(size_t)d * LL + lk + j]);
            Ks[d * PK + j + 0] = f2tff(xk.x);
            Ks[d * PK + j + 1] = f2tff(xk.y);
            Ks[d * PK + j + 2] = f2tff(xk.z);
            Ks[d * PK + j + 3] = f2tff(xk.w);
            float4 xv = *reinterpret_cast<const float4*>(&vb[(size_t)d * LL + lk + j]);
            Vs[d * PV + j + 0] = f2tff(xv.x);
            Vs[d * PV + j + 1] = f2tff(xv.y);
            Vs[d * PV + j + 2] = f2tff(xv.z);
            Vs[d * PV + j + 3] = f2tff(xv.w);
        }
        __syncthreads();

        // ---- S quarter = Q K^T: 2 m-tiles x 4 n-tiles ----
        float s[2][4][4];
        #pragma unroll
        for (int mt = 0; mt < 2; mt++)
            #pragma unroll
            for (int nt = 0; nt < 4; nt++)
                #pragma unroll
                for (int c = 0; c < 4; c++) s[mt][nt][c] = 0.f;
        #pragma unroll
        for (int kt = 0; kt < 8; kt++) {
            int kk = kt * 8;
            unsigned b[4][2];
            #pragma unroll
            for (int nt = 0; nt < 4; nt++) {
                int col = wn * 32 + nt * 8 + g;
                b[nt][0] = __float_as_uint(Ks[(kk + t4) * PK + col]);
                b[nt][1] = __float_as_uint(Ks[(kk + t4 + 4) * PK + col]);
            }
            #pragma unroll
            for (int nt = 0; nt < 4; nt++) {
                mma_tf32(s[0][nt], qa[kt][0], b[nt][0], b[nt][1]);
                mma_tf32(s[1][nt], qa[kt][1], b[nt][0], b[nt][1]);
            }
        }

        // ---- partial row max over this warp's 32 cols ----
        float pmax[2][2];
        #pragma unroll
        for (int mt = 0; mt < 2; mt++) {
            float a0 = -INFINITY, a1 = -INFINITY;
            #pragma unroll
            for (int nt = 0; nt < 4; nt++) {
                a0 = fmaxf(a0, fmaxf(s[mt][nt][0], s[mt][nt][1]));
                a1 = fmaxf(a1, fmaxf(s[mt][nt][2], s[mt][nt][3]));
            }
            a0 = fmaxf(a0, __shfl_xor_sync(0xffffffffu, a0, 1));
            a0 = fmaxf(a0, __shfl_xor_sync(0xffffffffu, a0, 2));
            a1 = fmaxf(a1, __shfl_xor_sync(0xffffffffu, a1, 1));
            a1 = fmaxf(a1, __shfl_xor_sync(0xffffffffu, a1, 2));
            pmax[mt][0] = a0; pmax[mt][1] = a1;
        }
        if (t4 == 0) {
            #pragma unroll
            for (int mt = 0; mt < 2; mt++) {
                stats[wn * 64 + rbase + mt * 16]     = pmax[mt][0];
                stats[wn * 64 + rbase + mt * 16 + 8] = pmax[mt][1];
            }
        }
        __syncthreads();  // stats ready

        // ---- global mnew, corrections ----
        float corr[2][2];
        #pragma unroll
        for (int mt = 0; mt < 2; mt++) {
            #pragma unroll
            for (int rr = 0; rr < 2; rr++) {
                int row = rbase + mt * 16 + rr * 8;
                float other = stats[(wn ^ 1) * 64 + row];
                float mnew = fmaxf(m[mt][rr], fmaxf(pmax[mt][rr], other));
                corr[mt][rr] = ex2f(m[mt][rr] - mnew);
                m[mt][rr] = mnew;
                ls[mt][rr] *= corr[mt][rr];
            }
        }

        // ---- exp, store P quarter, partial sums ----
        float* Ps = QPs;
        #pragma unroll
        for (int mt = 0; mt < 2; mt++) {
            float rs0 = 0.f, rs1 = 0.f;
            int row = rbase + mt * 16;
            #pragma unroll
            for (int nt = 0; nt < 4; nt++) {
                float p00 = ex2f(s[mt][nt][0] - m[mt][0]);
                float p01 = ex2f(s[mt][nt][1] - m[mt][0]);
                float p10 = ex2f(s[mt][nt][2] - m[mt][1]);
                float p11 = ex2f(s[mt][nt][3] - m[mt][1]);
                rs0 += p00 + p01;
                rs1 += p10 + p11;
                int colc = wn * 32 + nt * 8 + 2 * t4;
                *reinterpret_cast<float2*>(&Ps[row * PP + colc]) =
                    make_float2(f2tff(p00), f2tff(p01));
                *reinterpret_cast<float2*>(&Ps[(row + 8) * PP + colc]) =
                    make_float2(f2tff(p10), f2tff(p11));
            }
            rs0 += __shfl_xor_sync(0xffffffffu, rs0, 1);
            rs0 += __shfl_xor_sync(0xffffffffu, rs0, 2);
            rs1 += __shfl_xor_sync(0xffffffffu, rs1, 1);
            rs1 += __shfl_xor_sync(0xffffffffu, rs1, 2);
            ls[mt][0] += rs0;
            ls[mt][1] += rs1;
        }
        // scale O
        #pragma unroll
        for (int mt = 0; mt < 2; mt++)
            #pragma unroll
            for (int nt = 0; nt < 4; nt++) {
                o[mt][nt][0] *= corr[mt][0]; o[mt][nt][1] *= corr[mt][0];
                o[mt][nt][2] *= corr[mt][1]; o[mt][nt][3] *= corr[mt][1];
            }
        __syncthreads();  // full P tile ready

        // ---- O += P V: A = P rows (k=j full 64), B = V cols wn*32+nt*8 ----
        #pragma unroll
        for (int kt = 0; kt < 8; kt++) {
            int kk = kt * 8;
            unsigned a[2][4];
            #pragma unroll
            for (int mt = 0; mt < 2; mt++) {
                int row = rbase + mt * 16;
                a[mt][0] = __float_as_uint(Ps[row * PP + kk + t4]);
                a[mt][1] = __float_as_uint(Ps[(row + 8) * PP + kk + t4]);
                a[mt][2] = __float_as_uint(Ps[row * PP + kk + t4 + 4]);
                a[mt][3] = __float_as_uint(Ps[(row + 8) * PP + kk + t4 + 4]);
            }
            unsigned b[4][2];
            #pragma unroll
            for (int nt = 0; nt < 4; nt++) {
                int dcol = wn * 32 + nt * 8 + g;
                b[nt][0] = __float_as_uint(Vs[dcol * PV + kk + t4]);
                b[nt][1] = __float_as_uint(Vs[dcol * PV + kk + t4 + 4]);
            }
            #pragma unroll
            for (int nt = 0; nt < 4; nt++) {
                mma_tf32(o[0][nt], a[0], b[nt][0], b[nt][1]);
                mma_tf32(o[1][nt], a[1], b[nt][0], b[nt][1]);
            }
        }
    }

    // ---- combine lsum across n-warps ----
    __syncthreads();
    if (t4 == 0) {
        #pragma unroll
        for (int mt = 0; mt < 2; mt++) {
            stats[wn * 64 + rbase + mt * 16]     = ls[mt][0];
            stats[wn * 64 + rbase + mt * 16 + 8] = ls[mt][1];
        }
    }
    __syncthreads();
    float inv[2][2];
    #pragma unroll
    for (int mt = 0; mt < 2; mt++)
        #pragma unroll
        for (int rr = 0; rr < 2; rr++) {
            int row = rbase + mt * 16 + rr * 8;
            inv[mt][rr] = 1.f / (ls[mt][rr] + stats[(wn ^ 1) * 64 + row]);
        }

    // ---- stage O^T [d][i] pad PV into Ks region, coalesced write ----
    float* Os = Ks;
    #pragma unroll
    for (int mt = 0; mt < 2; mt++) {
        int i = rbase + mt * 16;
        #pragma unroll
        for (int nt = 0; nt < 4; nt++) {
            int d = wn * 32 + nt * 8 + 2 * t4;
            Os[(d    ) * PV + i]     = f2tff(o[mt][nt][0] * inv[mt][0]);
            Os[(d + 1) * PV + i]     = f2tff(o[mt][nt][1] * inv[mt][0]);
            Os[(d    ) * PV + i + 8] = f2tff(o[mt][nt][2] * inv[mt][1]);
            Os[(d + 1) * PV + i + 8] = f2tff(o[mt][nt][3] * inv[mt][1]);
        }
    }
    __syncthreads();
    const size_t cbase = (size_t)n * CC + h * DH;
    #pragma unroll
    for (int r = 0; r < 8; r++) {
        int idx = r * 512 + tid * 4;
        int d = idx >> 6, i = idx & 63;
        float4 val = *reinterpret_cast<const float4*>(&Os[d * PV + i]);
        *reinterpret_cast<float4*>(&ao[(cbase + d) * LL + l0 + i]) = val;
    }
}

// ---------------------------------------------------------------------------
extern "C" void kernel_launch(void* const* d_in, const int* in_sizes, int n_in,
                              void* d_out, int out_size) {
    const float* x     = (const float*)d_in[0];
    const float* gamma = (const float*)d_in[1];
    const float* beta  = (const float*)d_in[2];
    const float* Wq    = (const float*)d_in[3];
    const float* Wk    = (const float*)d_in[4];
    const float* Wv    = (const float*)d_in[5];
    const float* Wp    = (const float*)d_in[6];
    const float* bp    = (const float*)d_in[7];
    float* out = (float*)d_out;

    // One-time scratch address lookup + smem attr set (deterministic, cached)
    static float *xn = nullptr, *q, *k, *v, *ao, *wt;
    static size_t attn_smem =
        (size_t)(64 * PK + 64 * PV + 64 * PK + 128) * sizeof(float);
    if (!xn) {
        cudaGetSymbolAddress((void**)&xn, g_xn);
        cudaGetSymbolAddress((void**)&q,  g_q);
        cudaGetSymbolAddress((void**)&k,  g_k);
        cudaGetSymbolAddress((void**)&v,  g_v);
        cudaGetSymbolAddress((void**)&ao, g_ao);
        cudaGetSymbolAddress((void**)&wt, g_wt);
        cudaFuncSetAttribute(attn_tc_kernel,
                             cudaFuncAttributeMaxDynamicSharedMemorySize,
                             (int)attn_smem);
    }

    // Weight tf32 prep + GroupNorm (independent)
    wcvt_kernel<<<CC * CC / (256 * 4), 256>>>(Wq, Wk, Wv, Wp, wt);
    gn_kernel<<<NB * GROUPS, 256>>>(x, gamma, beta, xn);

    // Fused QKV projection (tensor cores)
    dim3 pgrid(LL / 64, CC / 64, NB);
    qkv_tc_kernel<<<pgrid, 128>>>(xn, wt, q, k, v);

    // Flash attention (tensor cores, tf32, 2x2 warp tiling)
    attn_tc_kernel<<<dim3(LL / 64, NB * HEADS), 128, attn_smem>>>(q, k, v, ao);

    // Output projection (+bias) straight into d_out (tensor cores)
    oproj_tc_kernel<<<pgrid, 128>>>(ao, wt + 3 * CC * CC, bp, out);
}